// round 2
// baseline (speedup 1.0000x reference)
#include <cuda_runtime.h>
#include <cuda_bf16.h>

namespace {

constexpr int NQ     = 12;
constexpr int DIM    = 4096;   // 2^12
constexpr int LAYERS = 8;
constexpr int FEAT   = 3072;
constexpr int NCLASS = 10;
constexpr int TPB    = 64;     // threads per CTA; each holds 64 amplitudes

// State layout, "arrangement A": thread t, register r  <->  amplitude index i = (t<<6) | r
//   (bits 0..5 = r are LOCAL, bits 6..11 = t are THREAD bits)
// "arrangement B" (after transpose): thread t, register r <-> index (r<<6) | t
//   (bits 6..11 LOCAL, bits 0..5 THREAD)
//
// Qubit q of the reference maps to bit position p = 11 - q (qubit 0 is MSB).
// The per-layer CNOT chain [CNOT(10,11); CNOT(i,i+1) for i=9..0] is, in bit space,
// targets 0..10 with controls 1..11, each control read before modification:
// net basis permutation  F(b) = b ^ (b >> 1)  (binary -> Gray code).

__global__ void __launch_bounds__(TPB, 8) qnn_kernel(
    const float* __restrict__ x,       // [B, 3072]
    const float* __restrict__ angles,  // [8, 12]
    const float* __restrict__ W,       // [10, 4096]
    const float* __restrict__ bias,    // [10]
    float* __restrict__ out)           // [B, 10]
{
    __shared__ float s_c[LAYERS][NQ];   // cos, indexed by [layer][bit position]
    __shared__ float s_s[LAYERS][NQ];   // sin
    __shared__ float sbuf[64 * 65];     // state exchange, pad-65 => conflict-free
    __shared__ float sred[32];          // reductions

    const int t  = threadIdx.x;
    const int bb = blockIdx.x;

    // Trig table: angle of qubit q drives the gate on bit p = 11 - q.
    for (int idx = t; idx < LAYERS * NQ; idx += TPB) {
        const int l = idx / NQ;
        const int q = idx - l * NQ;
        const float a = angles[idx];
        const int p = NQ - 1 - q;
        s_c[l][p] = cosf(a);
        s_s[l][p] = sinf(a);
    }

    // Load input row (pad 3072 -> 4096 with zeros), arrangement A.
    float v[64];
    if (t < FEAT / 64) {   // t < 48
        const float4* x4 = reinterpret_cast<const float4*>(x) + (size_t)bb * (FEAT / 4) + t * 16;
        #pragma unroll
        for (int i = 0; i < 16; i++) {
            const float4 w4 = x4[i];
            v[4*i+0] = w4.x; v[4*i+1] = w4.y; v[4*i+2] = w4.z; v[4*i+3] = w4.w;
        }
    } else {
        #pragma unroll
        for (int r = 0; r < 64; r++) v[r] = 0.0f;
    }

    // L2 normalization.
    float ssq = 0.0f;
    #pragma unroll
    for (int r = 0; r < 64; r++) ssq = fmaf(v[r], v[r], ssq);
    #pragma unroll
    for (int o = 16; o > 0; o >>= 1) ssq += __shfl_xor_sync(0xffffffffu, ssq, o);
    if ((t & 31) == 0) sred[t >> 5] = ssq;
    __syncthreads();   // also publishes the trig table
    const float rn = rsqrtf(sred[0] + sred[1]);
    #pragma unroll
    for (int r = 0; r < 64; r++) v[r] *= rn;

    #pragma unroll 1
    for (int l = 0; l < LAYERS; l++) {
        // ---- Ry gates on bits 0..5 (local in arrangement A) ----
        #pragma unroll
        for (int p = 0; p < 6; p++) {
            const float c = s_c[l][p];
            const float s = s_s[l][p];
            const int m = 1 << p;
            #pragma unroll
            for (int lo = 0; lo < 64; lo += 2 * m)
                #pragma unroll
                for (int k = 0; k < m; k++) {
                    const int r0 = lo + k, r1 = r0 + m;
                    const float a0 = v[r0], a1 = v[r1];
                    v[r0] = c * a0 - s * a1;       // bit=0 output
                    v[r1] = fmaf(s, a0, c * a1);   // bit=1 output
                }
        }

        // ---- transpose A -> B through shared ----
        __syncthreads();
        #pragma unroll
        for (int r = 0; r < 64; r++) sbuf[t * 65 + r] = v[r];
        __syncthreads();
        #pragma unroll
        for (int r = 0; r < 64; r++) v[r] = sbuf[r * 65 + t];

        // ---- Ry gates on bits 6..11 (local in arrangement B) ----
        #pragma unroll
        for (int p = 0; p < 6; p++) {
            const float c = s_c[l][p + 6];
            const float s = s_s[l][p + 6];
            const int m = 1 << p;
            #pragma unroll
            for (int lo = 0; lo < 64; lo += 2 * m)
                #pragma unroll
                for (int k = 0; k < m; k++) {
                    const int r0 = lo + k, r1 = r0 + m;
                    const float a0 = v[r0], a1 = v[r1];
                    v[r0] = c * a0 - s * a1;
                    v[r1] = fmaf(s, a0, c * a1);
                }
        }

        // ---- CNOT chain (Gray permutation) scatter, landing in arrangement A ----
        __syncthreads();
        #pragma unroll
        for (int r = 0; r < 64; r++) {
            const int bidx = (r << 6) | t;          // true index in arrangement B
            const int j = bidx ^ (bidx >> 1);       // destination index after CNOT chain
            sbuf[(j >> 6) * 65 + (j & 63)] = v[r];
        }
        __syncthreads();
        #pragma unroll
        for (int r = 0; r < 64; r++) v[r] = sbuf[t * 65 + r];
    }

    // ---- probabilities ----
    #pragma unroll
    for (int r = 0; r < 64; r++) v[r] = v[r] * v[r];

    // ---- readout: out[k] = sum_i probs[i] * W[k,i] + b[k] ----
    #pragma unroll 1
    for (int k = 0; k < NCLASS; k++) {
        const float4* w4 = reinterpret_cast<const float4*>(W + (size_t)k * DIM) + t * 16;
        float a = 0.0f;
        #pragma unroll
        for (int i = 0; i < 16; i++) {
            const float4 w = w4[i];
            a = fmaf(v[4*i+0], w.x, a);
            a = fmaf(v[4*i+1], w.y, a);
            a = fmaf(v[4*i+2], w.z, a);
            a = fmaf(v[4*i+3], w.w, a);
        }
        #pragma unroll
        for (int o = 16; o > 0; o >>= 1) a += __shfl_xor_sync(0xffffffffu, a, o);
        if ((t & 31) == 0) sred[(t >> 5) * NCLASS + k] = a;
    }
    __syncthreads();
    if (t < NCLASS)
        out[bb * NCLASS + t] = sred[t] + sred[NCLASS + t] + bias[t];
}

} // namespace

extern "C" void kernel_launch(void* const* d_in, const int* in_sizes, int n_in,
                              void* d_out, int out_size) {
    const float* x      = (const float*)d_in[0];
    const float* angles = (const float*)d_in[1];
    const float* W      = (const float*)d_in[2];
    const float* bias   = (const float*)d_in[3];
    const int batch = in_sizes[0] / FEAT;   // 2048
    qnn_kernel<<<batch, TPB>>>(x, angles, W, bias, (float*)d_out);
}

// round 3
// speedup vs baseline: 1.1849x; 1.1849x over previous
#include <cuda_runtime.h>
#include <cuda_bf16.h>

namespace {

constexpr int NQ     = 12;
constexpr int DIM    = 4096;
constexpr int LAYERS = 8;
constexpr int FEAT   = 3072;
constexpr int NCLASS = 10;
constexpr int TPB    = 128;   // threads per CTA (one state per CTA)
constexpr int AMPS   = 32;    // amplitudes per thread
constexpr int RS     = 33;    // smem row stride (floats), conflict-free

// Arrangement A: amplitude index i = (t<<5) | r    (bits 0-4 local regs,
//   bits 5-9 lane bits, bits 10-11 warp bits)
// Arrangement B: amplitude index i = (r<<7) | t    (bits 7-11 local regs,
//   bits 0-4 lane bits, bits 5-6 warp bits)
//
// Per layer: gates bits 0-4 local (A), bits 5-6 via shfl_xor (lane bits 0,1 in A),
// transpose A->B, gates bits 7-11 local (B), then CNOT-chain Gray permutation
// j = i ^ (i>>1) fused into the scatter back to arrangement A.

__global__ void __launch_bounds__(TPB, 6) qnn_kernel(
    const float* __restrict__ x,       // [B, 3072]
    const float* __restrict__ angles,  // [8, 12]
    const float* __restrict__ W,       // [10, 4096]
    const float* __restrict__ bias,    // [10]
    float* __restrict__ out)           // [B, 10]
{
    __shared__ float s_c[LAYERS][NQ];
    __shared__ float s_s[LAYERS][NQ];
    __shared__ float bufA[128 * RS];   // transpose buffer
    __shared__ float bufB[128 * RS];   // gray-scatter buffer
    __shared__ float sred[4 * NCLASS]; // reductions (norm uses [0..3])

    const int t    = threadIdx.x;
    const int lane = t & 31;
    const int warp = t >> 5;
    const int bb   = blockIdx.x;

    // Trig table: qubit q acts on bit position p = 11 - q.
    if (t < LAYERS * NQ) {
        const int l = t / NQ;
        const int q = t - l * NQ;
        const float a = angles[t];
        const int p = NQ - 1 - q;
        s_c[l][p] = cosf(a);
        s_s[l][p] = sinf(a);
    }

    // Load input row (pad 3072 -> 4096), arrangement A.
    float v[AMPS];
    if (t < FEAT / AMPS) {   // t < 96
        const float4* x4 = reinterpret_cast<const float4*>(x)
                         + (size_t)bb * (FEAT / 4) + t * (AMPS / 4);
        #pragma unroll
        for (int i = 0; i < AMPS / 4; i++) {
            const float4 w4 = x4[i];
            v[4*i+0] = w4.x; v[4*i+1] = w4.y; v[4*i+2] = w4.z; v[4*i+3] = w4.w;
        }
    } else {
        #pragma unroll
        for (int r = 0; r < AMPS; r++) v[r] = 0.0f;
    }

    // L2 normalization across the 128-thread CTA.
    float ssq = 0.0f;
    #pragma unroll
    for (int r = 0; r < AMPS; r++) ssq = fmaf(v[r], v[r], ssq);
    #pragma unroll
    for (int o = 16; o > 0; o >>= 1) ssq += __shfl_xor_sync(0xffffffffu, ssq, o);
    if (lane == 0) sred[warp] = ssq;
    __syncthreads();   // also publishes trig table
    const float rn = rsqrtf(sred[0] + sred[1] + sred[2] + sred[3]);
    #pragma unroll
    for (int r = 0; r < AMPS; r++) v[r] *= rn;

    const int g_t   = t ^ (t >> 1);                 // 7-bit Gray of thread id
    const int baseA = t * RS;                       // A read/write base
    const int baseB = warp * RS + lane;             // B read base (+ rp*4*RS)

    #pragma unroll 1
    for (int l = 0; l < LAYERS; l++) {
        // ---- gates on bits 0..4 (register butterflies) ----
        #pragma unroll
        for (int p = 0; p < 5; p++) {
            const float c = s_c[l][p];
            const float s = s_s[l][p];
            const int m = 1 << p;
            #pragma unroll
            for (int lo = 0; lo < AMPS; lo += 2 * m)
                #pragma unroll
                for (int k = 0; k < m; k++) {
                    const int r0 = lo + k, r1 = r0 + m;
                    const float a0 = v[r0], a1 = v[r1];
                    v[r0] = c * a0 - s * a1;
                    v[r1] = fmaf(s, a0, c * a1);
                }
        }

        // ---- gates on bits 5,6 via shfl_xor (lane bits 0,1) ----
        #pragma unroll
        for (int p = 5; p < 7; p++) {
            const float c = s_c[l][p];
            const float s = s_s[l][p];
            const int mask = 1 << (p - 5);
            const float se = (lane & mask) ? s : -s;  // bit=0: -s*partner; bit=1: +s*partner
            #pragma unroll
            for (int r = 0; r < AMPS; r++) {
                const float pr = __shfl_xor_sync(0xffffffffu, v[r], mask);
                v[r] = fmaf(se, pr, c * v[r]);
            }
        }

        // ---- transpose A -> B (bufA) ----
        #pragma unroll
        for (int r = 0; r < AMPS; r++) bufA[baseA + r] = v[r];
        __syncthreads();
        #pragma unroll
        for (int rp = 0; rp < AMPS; rp++) v[rp] = bufA[baseB + rp * 4 * RS];

        // ---- gates on bits 7..11 (register butterflies in B) ----
        #pragma unroll
        for (int p = 0; p < 5; p++) {
            const float c = s_c[l][p + 7];
            const float s = s_s[l][p + 7];
            const int m = 1 << p;
            #pragma unroll
            for (int lo = 0; lo < AMPS; lo += 2 * m)
                #pragma unroll
                for (int k = 0; k < m; k++) {
                    const int r0 = lo + k, r1 = r0 + m;
                    const float a0 = v[r0], a1 = v[r1];
                    v[r0] = c * a0 - s * a1;
                    v[r1] = fmaf(s, a0, c * a1);
                }
        }

        // ---- Gray scatter B -> A (bufB): j = i ^ (i>>1), i = (rp<<7)|t ----
        #pragma unroll
        for (int rp = 0; rp < AMPS; rp++) {
            const int K = (rp << 7) ^ (rp << 6);    // compile-time per rp
            const int j = K ^ g_t;
            bufB[(j >> 5) * RS + (j & 31)] = v[rp];
        }
        __syncthreads();
        #pragma unroll
        for (int r = 0; r < AMPS; r++) v[r] = bufB[baseA + r];
    }

    // ---- probabilities ----
    #pragma unroll
    for (int r = 0; r < AMPS; r++) v[r] = v[r] * v[r];

    // ---- readout: out[k] = sum_i probs[i] * W[k,i] + b[k] ----
    #pragma unroll 1
    for (int k = 0; k < NCLASS; k++) {
        const float4* w4 = reinterpret_cast<const float4*>(W + (size_t)k * DIM)
                         + t * (AMPS / 4);
        float a = 0.0f;
        #pragma unroll
        for (int i = 0; i < AMPS / 4; i++) {
            const float4 w = w4[i];
            a = fmaf(v[4*i+0], w.x, a);
            a = fmaf(v[4*i+1], w.y, a);
            a = fmaf(v[4*i+2], w.z, a);
            a = fmaf(v[4*i+3], w.w, a);
        }
        #pragma unroll
        for (int o = 16; o > 0; o >>= 1) a += __shfl_xor_sync(0xffffffffu, a, o);
        if (lane == 0) sred[k * 4 + warp] = a;
    }
    __syncthreads();
    if (t < NCLASS)
        out[bb * NCLASS + t] = sred[t * 4 + 0] + sred[t * 4 + 1]
                             + sred[t * 4 + 2] + sred[t * 4 + 3] + bias[t];
}

} // namespace

extern "C" void kernel_launch(void* const* d_in, const int* in_sizes, int n_in,
                              void* d_out, int out_size) {
    const float* x      = (const float*)d_in[0];
    const float* angles = (const float*)d_in[1];
    const float* W      = (const float*)d_in[2];
    const float* bias   = (const float*)d_in[3];
    const int batch = in_sizes[0] / FEAT;   // 2048
    qnn_kernel<<<batch, TPB>>>(x, angles, W, bias, (float*)d_out);
}